// round 6
// baseline (speedup 1.0000x reference)
#include <cuda_runtime.h>
#include <stdint.h>

// Depthwise 3x3 conv (256 ch x 2 filters) fused with butterfly wing-swap add.
//   out[c]  = conv(x[c],  w[2c])   + conv(x[cp], w[2cp+1])
//   out[cp] = conv(x[cp], w[2cp])  + conv(x[c],  w[2c+1]),  cp = c+4 within butterfly
// Persistent blocks, half-plane (28-row) tiles, double-buffered cp.async pipeline.
// Smem layout: channel-interleaved float2 (x_c, x_cp) per cell -> LDS.64 feeds
// fma.rn.f32x2 directly. Packed weights staged in shared per tile.

#define CH 256
#define HW 56
#define PLANE (HW * HW)
#define ST2 61                 // float2 elements per smem row (odd -> conflict-free)
#define TROWS 30               // 28 data rows + 2 halo slots
#define SPLANE2 (TROWS * ST2)  // 1830 float2 per buffer
#define NTHREADS 224           // 7 warps: 14 items/tile = exactly 2 per warp
#define NTILES 8192            // 32 batch * 128 pairs * 2 halves
#define GRID 608               // 4 blocks/SM * 152 SMs

typedef unsigned long long ull;

__device__ __forceinline__ ull fma2(ull a, ull b, ull c) {
    ull d; asm("fma.rn.f32x2 %0, %1, %2, %3;" : "=l"(d) : "l"(a), "l"(b), "l"(c)); return d;
}
__device__ __forceinline__ ull pack2(float lo, float hi) {
    ull r; asm("mov.b64 %0, {%1, %2};" : "=l"(r) : "f"(lo), "f"(hi)); return r;
}
__device__ __forceinline__ float2 unpack2(ull v) {
    float2 r; asm("mov.b64 {%0, %1}, %2;" : "=f"(r.x), "=f"(r.y) : "l"(v)); return r;
}

__global__ __launch_bounds__(NTHREADS, 4)
void conv_butterfly_kernel(const float* __restrict__ x,
                           const float* __restrict__ w,
                           float* __restrict__ out)
{
    extern __shared__ float2 sm[];               // [2 buffers][SPLANE2]
    __shared__ __align__(16) ull wsm[18];        // per-dr groups: Wc0,Wc1,Wc2,Wp0,Wp1,Wp2

    const int tid    = threadIdx.x;
    const int warpid = tid >> 5;                 // 0..6
    const int lane   = tid & 31;
    const int lr     = lane & 3;
    const int lc     = lane >> 2;
    const uint32_t smem0 = (uint32_t)__cvta_generic_to_shared(sm);

    // ---- zero pad columns (0 = left halo, 57..60 incl. right halo 57) once; never rewritten
    for (int i = tid; i < 2 * TROWS * 5; i += NTHREADS) {
        const int rs = i / 5;                    // buffer*TROWS + row slot
        const int pc = i % 5;
        const int col = (pc == 0) ? 0 : (56 + pc);
        sm[rs * ST2 + col] = make_float2(0.f, 0.f);
    }

    // ---- prefetch half-tile t into buffer b (3360 4B copies, zfill OOB rows)
    auto prefetch = [&](int t, int b) {
        const int half = t & 1;
        const int p    = (t >> 1) & 127;
        const int n    = t >> 8;
        const int c    = ((p >> 2) << 3) + (p & 3);
        const int h0   = half * 28;
        const float* base = x + ((size_t)n * CH + c) * PLANE;
        #pragma unroll
        for (int k = 0; k < 15; k++) {
            const int i    = tid + k * NTHREADS;         // 0..3359
            const int slot = i / 112;                    // 0..29
            const int rem  = i - slot * 112;
            const int ch   = rem & 1;
            const int col  = rem >> 1;                   // 0..55
            const int h    = h0 - 1 + slot;              // -1..56
            const int sz   = (h >= 0 && h < HW) ? 4 : 0;
            const int hc   = min(max(h, 0), HW - 1);
            const float* src = base + ch * (4 * PLANE) + hc * HW + col;
            const uint32_t dst = smem0 +
                (uint32_t)(((b * SPLANE2 + slot * ST2 + 1 + col) << 3) + (ch << 2));
            asm volatile("cp.async.ca.shared.global [%0], [%1], 4, %2;"
                         :: "r"(dst), "l"(src), "r"(sz));
        }
    };

    int t = blockIdx.x;
    int b = 0;
    if (t < NTILES) prefetch(t, 0);
    asm volatile("cp.async.commit_group;");

    while (t < NTILES) {
        const int tn = t + GRID;
        if (tn < NTILES) prefetch(tn, b ^ 1);
        asm volatile("cp.async.commit_group;");

        const int half = t & 1;
        const int p    = (t >> 1) & 127;
        const int n    = t >> 8;
        const int c    = ((p >> 2) << 3) + (p & 3);
        const int h0   = half * 28;

        // stage packed weights in shared (18 threads, one ull each)
        if (tid < 18) {
            const float* wa = w + 18 * c;         // [w2c | w2c+1]
            const float* wb = w + 18 * (c + 4);   // [w2cp | w2cp+1]
            const int dr = tid / 6, sl = tid % 6;
            ull v;
            if (sl < 3) { const int k = dr * 3 + sl;     v = pack2(__ldg(wa + k),     __ldg(wb + 9 + k)); }
            else        { const int k = dr * 3 + sl - 3; v = pack2(__ldg(wa + 9 + k), __ldg(wb + k)); }
            wsm[tid] = v;
        }

        asm volatile("cp.async.wait_group 1;");
        __syncthreads();

        const ull* sbase = (const ull*)sm + b * SPLANE2;
        float* o0 = out + ((size_t)n * CH + c) * PLANE + h0 * HW;
        float* o1 = o0 + 4 * PLANE;

        const int rl = (warpid << 2) + lr;        // local output row 0..27

        #pragma unroll
        for (int pp = 0; pp < 2; pp++) {
            const int strip = (pp << 3) + lc;     // 0..15, active < 14
            if (strip < 14) {
                const int c0 = strip << 2;
                ull a0 = 0, a1 = 0, a2 = 0, a3 = 0;   // -> out[c]
                ull q0 = 0, q1 = 0, q2 = 0, q3 = 0;   // -> out[cp]
                #pragma unroll
                for (int dr = 0; dr < 3; dr++) {
                    const ull* qp = sbase + (rl + dr) * ST2 + c0;  // elements c0..c0+5
                    const ull v0 = qp[0], v1 = qp[1], v2 = qp[2];
                    const ull v3 = qp[3], v4 = qp[4], v5 = qp[5];
                    const ulonglong2 wA = *(const ulonglong2*)(wsm + dr * 6);
                    const ulonglong2 wB = *(const ulonglong2*)(wsm + dr * 6 + 2);
                    const ulonglong2 wC = *(const ulonglong2*)(wsm + dr * 6 + 4);
                    const ull wc0 = wA.x, wc1 = wA.y, wc2 = wB.x;
                    const ull wp0 = wB.y, wp1 = wC.x, wp2 = wC.y;

                    a0 = fma2(v0, wc0, a0); a0 = fma2(v1, wc1, a0); a0 = fma2(v2, wc2, a0);
                    a1 = fma2(v1, wc0, a1); a1 = fma2(v2, wc1, a1); a1 = fma2(v3, wc2, a1);
                    a2 = fma2(v2, wc0, a2); a2 = fma2(v3, wc1, a2); a2 = fma2(v4, wc2, a2);
                    a3 = fma2(v3, wc0, a3); a3 = fma2(v4, wc1, a3); a3 = fma2(v5, wc2, a3);

                    q0 = fma2(v0, wp0, q0); q0 = fma2(v1, wp1, q0); q0 = fma2(v2, wp2, q0);
                    q1 = fma2(v1, wp0, q1); q1 = fma2(v2, wp1, q1); q1 = fma2(v3, wp2, q1);
                    q2 = fma2(v2, wp0, q2); q2 = fma2(v3, wp1, q2); q2 = fma2(v4, wp2, q2);
                    q3 = fma2(v3, wp0, q3); q3 = fma2(v4, wp1, q3); q3 = fma2(v5, wp2, q3);
                }
                float2 u;
                float4 lo, hi;
                u = unpack2(a0); lo.x = u.x + u.y;
                u = unpack2(a1); lo.y = u.x + u.y;
                u = unpack2(a2); lo.z = u.x + u.y;
                u = unpack2(a3); lo.w = u.x + u.y;
                u = unpack2(q0); hi.x = u.x + u.y;
                u = unpack2(q1); hi.y = u.x + u.y;
                u = unpack2(q2); hi.z = u.x + u.y;
                u = unpack2(q3); hi.w = u.x + u.y;
                *(float4*)(o0 + rl * HW + c0) = lo;
                *(float4*)(o1 + rl * HW + c0) = hi;
            }
        }
        __syncthreads();      // protect buffer b and wsm before refill
        t = tn;
        b ^= 1;
    }
}

extern "C" void kernel_launch(void* const* d_in, const int* in_sizes, int n_in,
                              void* d_out, int out_size)
{
    const float* x = (const float*)d_in[0];
    const float* w = (const float*)d_in[1];
    float* out = (float*)d_out;
    (void)in_sizes; (void)n_in; (void)out_size;

    const int smem_bytes = 2 * SPLANE2 * (int)sizeof(float2);   // 29,280 B
    conv_butterfly_kernel<<<GRID, NTHREADS, smem_bytes>>>(x, w, out);
}